// round 4
// baseline (speedup 1.0000x reference)
#include <cuda_runtime.h>
#include <cuda_fp16.h>
#include <math.h>

#define NN 50000
#define EE 800000

// ---------------- scratch (static device globals; no allocations) ----------------
__device__ float  g_dinv[NN];
__device__ int    g_deg[NN];
__device__ int    g_rowptr[NN + 1];
__device__ int    g_bsum[256];
__device__ int    g_esrc[EE];
__device__ float  g_ew[EE];
__device__ float  g_h   [(size_t)NN * 64];       // inter-layer activations (fp32)
__device__ __half g_hh  [(size_t)NN * 64];       // fp16 mirror of h
__device__ __half g_b3h [(size_t)2 * NN * 64];   // fp16: out0 mirror (L1) / t1 output
__device__ float  g_buf0[(size_t)2 * NN * 64];   // out0 (for dense path)
__device__ float  g_agg [(size_t)2 * NN * 64];   // prop destination (pc / agg2)
__device__ float  g_buf2[(size_t)2 * NN * 64];   // t0 output / final per-k
__device__ float  g_buf4[(size_t)2 * NN * 64];   // dense1

// ---------------- setup kernels ----------------
__global__ void k_zero_int(int* p, int n) {
    int i = blockIdx.x * blockDim.x + threadIdx.x;
    if (i < n) p[i] = 0;
}
__global__ void k_deg(const int* __restrict__ col, int* __restrict__ deg, int E) {
    int e = blockIdx.x * blockDim.x + threadIdx.x;
    if (e < E) atomicAdd(&deg[col[e]], 1);
}
__global__ void k_dinv(const int* __restrict__ deg, float* __restrict__ dinv, int n) {
    int i = blockIdx.x * blockDim.x + threadIdx.x;
    if (i < n) {
        int d = deg[i];
        dinv[i] = (d > 0) ? rsqrtf((float)d) : 0.f;
    }
}
__global__ void k_blocksum(const int* __restrict__ deg, int* __restrict__ bsum, int n) {
    __shared__ int s[256];
    int i = blockIdx.x * 256 + threadIdx.x;
    s[threadIdx.x] = (i < n) ? deg[i] : 0;
    __syncthreads();
    for (int o = 128; o > 0; o >>= 1) {
        if (threadIdx.x < o) s[threadIdx.x] += s[threadIdx.x + o];
        __syncthreads();
    }
    if (threadIdx.x == 0) bsum[blockIdx.x] = s[0];
}
__global__ void k_scanb(int* bsum, int nb) {
    __shared__ int s[256];
    int v = (threadIdx.x < nb) ? bsum[threadIdx.x] : 0;
    s[threadIdx.x] = v;
    __syncthreads();
    for (int o = 1; o < 256; o <<= 1) {
        int t = (threadIdx.x >= o) ? s[threadIdx.x - o] : 0;
        __syncthreads();
        s[threadIdx.x] += t;
        __syncthreads();
    }
    if (threadIdx.x < nb) bsum[threadIdx.x] = s[threadIdx.x] - v;
}
__global__ void k_scanfinal(const int* __restrict__ deg, const int* __restrict__ bsum,
                            int* __restrict__ rowptr, int n, int E) {
    __shared__ int s[256];
    int i = blockIdx.x * 256 + threadIdx.x;
    int v = (i < n) ? deg[i] : 0;
    s[threadIdx.x] = v;
    __syncthreads();
    for (int o = 1; o < 256; o <<= 1) {
        int t = (threadIdx.x >= o) ? s[threadIdx.x - o] : 0;
        __syncthreads();
        s[threadIdx.x] += t;
        __syncthreads();
    }
    if (i < n) rowptr[i] = bsum[blockIdx.x] + s[threadIdx.x] - v;
    if (i == 0 && blockIdx.x == 0) rowptr[n] = E;
}
__global__ void k_fill(const int* __restrict__ row, const int* __restrict__ col,
                       const float* __restrict__ dinv,
                       const int* __restrict__ rowptr, int* __restrict__ counter,
                       int* __restrict__ esrc, float* __restrict__ ew, int E) {
    int e = blockIdx.x * blockDim.x + threadIdx.x;
    if (e >= E) return;
    int r = row[e], t = col[e];
    int p = rowptr[t] + atomicAdd(&counter[t], 1);
    esrc[p] = r;
    ew[p] = dinv[r] * dinv[t];
}

// ---------------- message passing: CSR gather, fp16 source ----------------
// CH chunks of 8 halves per node (across all K planes); F8K chunks per plane.
template<int CH, int F8K>
__global__ void k_prop_h(const __half* __restrict__ src, float* __restrict__ dst,
                         const int* __restrict__ rowptr, const int* __restrict__ esrc,
                         const float* __restrict__ ew, int N, long sKh, long sKf) {
    int idx = blockIdx.x * blockDim.x + threadIdx.x;
    int n = idx / CH;
    if (n >= N) return;
    int c = idx - n * CH;
    int k = c / F8K;
    int cc = c - k * F8K;
    const int F = F8K * 8;
    const __half* sb = src + (long)k * sKh + cc * 8;
    float acc[8];
#pragma unroll
    for (int q = 0; q < 8; q++) acc[q] = 0.f;
    int s0 = rowptr[n], s1 = rowptr[n + 1];
    for (int j = s0; j < s1; j++) {
        int s = esrc[j];
        float wv = ew[j];
        uint4 u = *(const uint4*)(sb + (long)s * F);
        const __half2* hp = (const __half2*)&u;
#pragma unroll
        for (int q = 0; q < 4; q++) {
            float2 f = __half22float2(hp[q]);
            acc[2 * q]     += f.x * wv;
            acc[2 * q + 1] += f.y * wv;
        }
    }
    float* db = dst + (long)k * sKf + ((long)n * F + cc * 8);
    *(float4*)db       = make_float4(acc[0], acc[1], acc[2], acc[3]);
    *(float4*)(db + 4) = make_float4(acc[4], acc[5], acc[6], acc[7]);
}

// ---------------- fused SGEMM (8x8 micro-tile, split-A/split-B, fp16 mirror) ----------------
// C[k] = act( [A1|A2][k] @ [B1;B2][k] + D1[k] + alpha2*D2[k] + bias_scalar )
// meanMode: A-load = 0.5*(A1 + A2) over full Fin (mean over K=2).
template<int FO>
__global__ __launch_bounds__(16 * (FO / 8))
void k_gemm2(const float* __restrict__ A1, long a1K, int fin1, int lda1,
             const float* __restrict__ A2, long a2K, int lda2, int meanMode,
             const float* __restrict__ B1, long b1K,
             const float* __restrict__ B2, long b2K,
             int Fin,
             const float* __restrict__ D1, long dK,
             const float* __restrict__ D2, float alpha2,
             const float* __restrict__ bias,
             float* __restrict__ Cf, __half* __restrict__ Ch, long cK, long chK,
             int nRows, int act) {
    constexpr int TX = FO / 8;
    constexpr int NT = 16 * TX;
    const int k = blockIdx.z;
    A1 += (long)k * a1K;
    const float* a2 = A2 ? (A2 + (long)k * a2K) : nullptr;
    B1 += (long)k * b1K;
    const float* b2p = B2 ? (B2 + (long)k * b2K) : nullptr;
    const float* d1 = D1 ? (D1 + (long)k * dK) : nullptr;
    const float* d2 = D2 ? (D2 + (long)k * dK) : nullptr;
    float* cf = Cf ? (Cf + (long)k * cK) : nullptr;
    __half* ch = Ch ? (Ch + (long)k * chK) : nullptr;

    __shared__ float Bs[128][FO];
    __shared__ float As[16][136];

    const int tid = threadIdx.x;
    const int tx = tid % TX;
    const int ty = tid / TX;
    const int row0 = blockIdx.x * 128;

    for (int i = tid; i < Fin * FO; i += NT) {
        int r = i / FO;
        ((float*)Bs)[i] = (r < fin1) ? B1[i] : b2p[i - fin1 * FO];
    }

    float acc[8][8];
#pragma unroll
    for (int i = 0; i < 8; i++)
#pragma unroll
        for (int j = 0; j < 8; j++) acc[i][j] = 0.f;

    for (int kk0 = 0; kk0 < Fin; kk0 += 16) {
        __syncthreads();
        for (int i = tid; i < 128 * 16; i += NT) {
            int r = i >> 4, c = i & 15;
            int gr = row0 + r;
            int gc = kk0 + c;
            float v = 0.f;
            if (gr < nRows) {
                if (meanMode)
                    v = 0.5f * (A1[(long)gr * lda1 + gc] + a2[(long)gr * lda2 + gc]);
                else if (gc < fin1)
                    v = A1[(long)gr * lda1 + gc];
                else
                    v = a2[(long)gr * lda2 + gc - fin1];
            }
            As[c][r] = v;
        }
        __syncthreads();
#pragma unroll
        for (int kk = 0; kk < 16; kk++) {
            float4 aA = *(const float4*)&As[kk][ty * 8];
            float4 aB = *(const float4*)&As[kk][ty * 8 + 4];
            float4 bA = *(const float4*)&Bs[kk0 + kk][tx * 8];
            float4 bB = *(const float4*)&Bs[kk0 + kk][tx * 8 + 4];
            float av[8] = {aA.x, aA.y, aA.z, aA.w, aB.x, aB.y, aB.z, aB.w};
            float bv[8] = {bA.x, bA.y, bA.z, bA.w, bB.x, bB.y, bB.z, bB.w};
#pragma unroll
            for (int i = 0; i < 8; i++)
#pragma unroll
                for (int j = 0; j < 8; j++) acc[i][j] += av[i] * bv[j];
        }
    }

    float bvs = bias ? __ldg(bias) : 0.f;
#pragma unroll
    for (int i = 0; i < 8; i++) {
        int gr = row0 + ty * 8 + i;
        if (gr < nRows) {
            long base = (long)gr * FO + tx * 8;
            float v[8];
#pragma unroll
            for (int j = 0; j < 8; j++) {
                float t = acc[i][j];
                if (d1) t += d1[base + j];
                if (d2) t += alpha2 * d2[base + j];
                t += bvs;
                if (act) t = (t >= 0.f) ? t : 0.2f * t;
                v[j] = t;
            }
            if (cf) {
                *(float4*)(cf + base)     = make_float4(v[0], v[1], v[2], v[3]);
                *(float4*)(cf + base + 4) = make_float4(v[4], v[5], v[6], v[7]);
            }
            if (ch) {
                __half2 h0 = __floats2half2_rn(v[0], v[1]);
                __half2 h1 = __floats2half2_rn(v[2], v[3]);
                __half2 h2 = __floats2half2_rn(v[4], v[5]);
                __half2 h3 = __floats2half2_rn(v[6], v[7]);
                uint4 pk;
                pk.x = *(unsigned*)&h0; pk.y = *(unsigned*)&h1;
                pk.z = *(unsigned*)&h2; pk.w = *(unsigned*)&h3;
                *(uint4*)(ch + base) = pk;
            }
        }
    }
}

// y = relu(a + b) : sum over K=2 stacks + inter-layer ReLU, fp32 + fp16 mirror
__global__ void k_combine(const float4* __restrict__ a, const float4* __restrict__ b,
                          float4* __restrict__ o, __half2* __restrict__ oh, int n4) {
    int i = blockIdx.x * blockDim.x + threadIdx.x;
    if (i < n4) {
        float4 x = a[i], y = b[i];
        float4 r;
        r.x = fmaxf(x.x + y.x, 0.f);
        r.y = fmaxf(x.y + y.y, 0.f);
        r.z = fmaxf(x.z + y.z, 0.f);
        r.w = fmaxf(x.w + y.w, 0.f);
        o[i] = r;
        oh[2 * i]     = __floats2half2_rn(r.x, r.y);
        oh[2 * i + 1] = __floats2half2_rn(r.z, r.w);
    }
}

// warp-per-row log_softmax, C == 32 lanes
__global__ void k_logsoftmax(const float* __restrict__ in, float* __restrict__ out, int n) {
    int warp = (blockIdx.x * blockDim.x + threadIdx.x) >> 5;
    int lane = threadIdx.x & 31;
    if (warp >= n) return;
    float v = in[(long)warp * 32 + lane];
    float m = v;
#pragma unroll
    for (int o = 16; o > 0; o >>= 1) m = fmaxf(m, __shfl_xor_sync(0xffffffffu, m, o));
    float e = expf(v - m);
    float s = e;
#pragma unroll
    for (int o = 16; o > 0; o >>= 1) s += __shfl_xor_sync(0xffffffffu, s, o);
    out[(long)warp * 32 + lane] = v - m - logf(s);
}

// ---------------- host orchestration ----------------
extern "C" void kernel_launch(void* const* d_in, const int* in_sizes, int n_in,
                              void* d_out, int out_size) {
    const float* x = (const float*)d_in[0];
    const int* ei  = (const int*)d_in[1];
    const int E = in_sizes[1] / 2;
    const int N = in_sizes[0] / 128;
    const int* row = ei;
    const int* col = ei + E;

    float *dinv, *h, *b0, *ag, *b2, *b4, *ew;
    __half *hh, *b3h;
    int *deg, *rowptr, *bsum, *esrc;
    cudaGetSymbolAddress((void**)&dinv,   g_dinv);
    cudaGetSymbolAddress((void**)&deg,    g_deg);
    cudaGetSymbolAddress((void**)&rowptr, g_rowptr);
    cudaGetSymbolAddress((void**)&bsum,   g_bsum);
    cudaGetSymbolAddress((void**)&esrc,   g_esrc);
    cudaGetSymbolAddress((void**)&ew,     g_ew);
    cudaGetSymbolAddress((void**)&h,      g_h);
    cudaGetSymbolAddress((void**)&hh,     g_hh);
    cudaGetSymbolAddress((void**)&b3h,    g_b3h);
    cudaGetSymbolAddress((void**)&b0,     g_buf0);
    cudaGetSymbolAddress((void**)&ag,     g_agg);
    cudaGetSymbolAddress((void**)&b2,     g_buf2);
    cudaGetSymbolAddress((void**)&b4,     g_buf4);

    const int nb = (N + 255) / 256;

    // gcn_norm + destination-sorted CSR build
    k_zero_int<<<nb, 256>>>(deg, N);
    k_deg<<<(E + 255) / 256, 256>>>(col, deg, E);
    k_dinv<<<nb, 256>>>(deg, dinv, N);
    k_blocksum<<<nb, 256>>>(deg, bsum, N);
    k_scanb<<<1, 256>>>(bsum, nb);
    k_scanfinal<<<nb, 256>>>(deg, bsum, rowptr, N, E);
    k_zero_int<<<nb, 256>>>(deg, N);
    k_fill<<<(E + 255) / 256, 256>>>(row, col, dinv, rowptr, deg, esrc, ew, E);

    const long sK  = (long)N * 64;     // fp32 plane stride (F=64)
    const int gX   = (N + 127) / 128;

    // -------- Layer 1: Fin=128, FO=64, K=2, T=2 (non-commuted first prop) --------
    {
        const float* w  = (const float*)d_in[2];
        const float* iw = (const float*)d_in[3];
        const float* rw = (const float*)d_in[4];
        const float* dw = (const float*)d_in[5];
        const float* bb = (const float*)d_in[6];
        dim3 gg(gX, 1, 2);
        // out0 = x@iw  (fp32 for dense, fp16 mirror for prop)
        k_gemm2<64><<<gg, 128>>>(x, 0, 128, 128, nullptr, 0, 0, 0,
                                 iw, 128 * 64, nullptr, 0, 128,
                                 nullptr, 0, nullptr, 0.f, nullptr,
                                 b0, b3h, sK, sK, N, 0);
        // agg = prop(out0)
        k_prop_h<16, 8><<<(int)((((long)N * 16) + 255) / 256), 256>>>(b3h, ag, rowptr, esrc, ew, N, sK, sK);
        // out_t0 = leaky(agg + x@rw0 + b0)
        k_gemm2<64><<<gg, 128>>>(x, 0, 128, 128, nullptr, 0, 0, 0,
                                 rw, 128 * 64, nullptr, 0, 128,
                                 ag, sK, nullptr, 0.f, bb + 0,
                                 b2, nullptr, sK, 0, N, 1);
        // t1 = out_t0@W[0]  (fp16 only)
        k_gemm2<64><<<gg, 128>>>(b2, sK, 64, 64, nullptr, 0, 0, 0,
                                 w, 64 * 64, nullptr, 0, 64,
                                 nullptr, 0, nullptr, 0.f, nullptr,
                                 nullptr, b3h, 0, sK, N, 0);
        // agg2 = prop(t1)
        k_prop_h<16, 8><<<(int)((((long)N * 16) + 255) / 256), 256>>>(b3h, ag, rowptr, esrc, ew, N, sK, sK);
        // dense1 = mean_k(out0)@dw[1]
        k_gemm2<64><<<gg, 128>>>(b0, 0, 64, 64, b0 + sK, 0, 64, 1,
                                 dw + 2 * 64 * 64, 64 * 64, nullptr, 0, 64,
                                 nullptr, 0, nullptr, 0.f, nullptr,
                                 b4, nullptr, sK, 0, N, 0);
        // final = leaky(agg2 + x@rw1 + 0.6*dense1 + b1)
        k_gemm2<64><<<gg, 128>>>(x, 0, 128, 128, nullptr, 0, 0, 0,
                                 rw + 2 * 128 * 64, 128 * 64, nullptr, 0, 128,
                                 ag, sK, b4, 0.6f, bb + 1,
                                 b2, nullptr, sK, 0, N, 1);
        int n4 = (int)(sK / 4);
        k_combine<<<(n4 + 255) / 256, 256>>>((const float4*)b2, (const float4*)(b2 + sK),
                                             (float4*)h, (__half2*)hh, n4);
    }

    // -------- Layers 2-5: Fin=64, FO=64, K=2, T=2 (commuted first prop) --------
    for (int L = 1; L < 5; L++) {
        const float* w  = (const float*)d_in[2 + L * 5 + 0];
        const float* iw = (const float*)d_in[2 + L * 5 + 1];
        const float* rw = (const float*)d_in[2 + L * 5 + 2];
        const float* dw = (const float*)d_in[2 + L * 5 + 3];
        const float* bb = (const float*)d_in[2 + L * 5 + 4];
        dim3 gg(gX, 1, 2);
        // pc = prop(h)  (single shared plane)
        k_prop_h<8, 8><<<(int)((((long)N * 8) + 255) / 256), 256>>>(hh, ag, rowptr, esrc, ew, N, 0, 0);
        // out0 = h@iw (fp32, dense path only)
        k_gemm2<64><<<gg, 128>>>(h, 0, 64, 64, nullptr, 0, 0, 0,
                                 iw, 64 * 64, nullptr, 0, 64,
                                 nullptr, 0, nullptr, 0.f, nullptr,
                                 b0, nullptr, sK, 0, N, 0);
        // out_t0 = leaky([pc|h] @ [iw;rw0] + b0)
        k_gemm2<64><<<gg, 128>>>(ag, 0, 64, 64, h, 0, 64, 0,
                                 iw, 64 * 64, rw, 64 * 64, 128,
                                 nullptr, 0, nullptr, 0.f, bb + 0,
                                 b2, nullptr, sK, 0, N, 1);
        // t1 = out_t0@W[0]  (fp16 only)
        k_gemm2<64><<<gg, 128>>>(b2, sK, 64, 64, nullptr, 0, 0, 0,
                                 w, 64 * 64, nullptr, 0, 64,
                                 nullptr, 0, nullptr, 0.f, nullptr,
                                 nullptr, b3h, 0, sK, N, 0);
        // agg2 = prop(t1)
        k_prop_h<16, 8><<<(int)((((long)N * 16) + 255) / 256), 256>>>(b3h, ag, rowptr, esrc, ew, N, sK, sK);
        // dense1 = mean_k(out0)@dw[1]
        k_gemm2<64><<<gg, 128>>>(b0, 0, 64, 64, b0 + sK, 0, 64, 1,
                                 dw + 2 * 64 * 64, 64 * 64, nullptr, 0, 64,
                                 nullptr, 0, nullptr, 0.f, nullptr,
                                 b4, nullptr, sK, 0, N, 0);
        // final = leaky(agg2 + h@rw1 + 0.6*dense1 + b1)
        k_gemm2<64><<<gg, 128>>>(h, 0, 64, 64, nullptr, 0, 0, 0,
                                 rw + 2 * 64 * 64, 64 * 64, nullptr, 0, 64,
                                 ag, sK, b4, 0.6f, bb + 1,
                                 b2, nullptr, sK, 0, N, 1);
        int n4 = (int)(sK / 4);
        k_combine<<<(n4 + 255) / 256, 256>>>((const float4*)b2, (const float4*)(b2 + sK),
                                             (float4*)h, (__half2*)hh, n4);
    }

    // -------- Layer 6: Fin=64, FO=32, K=1, T=1 (commuted) --------
    {
        const float* iw = (const float*)d_in[2 + 5 * 5 + 1];
        const float* rw = (const float*)d_in[2 + 5 * 5 + 2];
        const float* bb = (const float*)d_in[2 + 5 * 5 + 4];
        // pc = prop(h)
        k_prop_h<8, 8><<<(int)((((long)N * 8) + 255) / 256), 256>>>(hh, ag, rowptr, esrc, ew, N, 0, 0);
        // out = leaky([pc|h] @ [iw;rw] + b0)
        dim3 gg(gX, 1, 1);
        k_gemm2<32><<<gg, 64>>>(ag, 0, 64, 64, h, 0, 64, 0,
                                iw, 64 * 32, rw, 64 * 32, 128,
                                nullptr, 0, nullptr, 0.f, bb + 0,
                                b2, nullptr, (long)N * 32, 0, N, 1);
        k_logsoftmax<<<(N + 7) / 8, 256>>>(b2, (float*)d_out, N);
    }
    (void)n_in; (void)out_size;
}

// round 5
// speedup vs baseline: 1.1750x; 1.1750x over previous
#include <cuda_runtime.h>
#include <cuda_fp16.h>
#include <math.h>

#define NN 50000
#define EE 800000

// ---------------- scratch (static device globals; no allocations) ----------------
__device__ float  g_dinv[NN];
__device__ int    g_deg[NN];
__device__ int    g_rowptr[NN + 1];
__device__ int    g_bsum[256];
__device__ int    g_esrc[EE];
__device__ float  g_ew[EE];
__device__ float  g_h   [(size_t)NN * 64];       // inter-layer activations (fp32)
__device__ __half g_hh  [(size_t)NN * 64];       // fp16 mirror of h
__device__ __half g_b3h [(size_t)2 * NN * 64];   // fp16: out0 mirror (L1) / t1 output
__device__ float  g_buf0[(size_t)2 * NN * 64];   // out0 (for dense path)
__device__ float  g_agg [(size_t)2 * NN * 64];   // prop destination (pc / agg2)
__device__ float  g_buf2[(size_t)2 * NN * 64];   // t0 output / final per-k
__device__ float  g_buf4[(size_t)2 * NN * 64];   // dense1

// ---------------- setup kernels ----------------
__global__ void k_zero_int(int* p, int n) {
    int i = blockIdx.x * blockDim.x + threadIdx.x;
    if (i < n) p[i] = 0;
}
__global__ void k_deg(const int* __restrict__ col, int* __restrict__ deg, int E) {
    int e = blockIdx.x * blockDim.x + threadIdx.x;
    if (e < E) atomicAdd(&deg[col[e]], 1);
}
__global__ void k_dinv(const int* __restrict__ deg, float* __restrict__ dinv, int n) {
    int i = blockIdx.x * blockDim.x + threadIdx.x;
    if (i < n) {
        int d = deg[i];
        dinv[i] = (d > 0) ? rsqrtf((float)d) : 0.f;
    }
}
__global__ void k_blocksum(const int* __restrict__ deg, int* __restrict__ bsum, int n) {
    __shared__ int s[256];
    int i = blockIdx.x * 256 + threadIdx.x;
    s[threadIdx.x] = (i < n) ? deg[i] : 0;
    __syncthreads();
    for (int o = 128; o > 0; o >>= 1) {
        if (threadIdx.x < o) s[threadIdx.x] += s[threadIdx.x + o];
        __syncthreads();
    }
    if (threadIdx.x == 0) bsum[blockIdx.x] = s[0];
}
__global__ void k_scanb(int* bsum, int nb) {
    __shared__ int s[256];
    int v = (threadIdx.x < nb) ? bsum[threadIdx.x] : 0;
    s[threadIdx.x] = v;
    __syncthreads();
    for (int o = 1; o < 256; o <<= 1) {
        int t = (threadIdx.x >= o) ? s[threadIdx.x - o] : 0;
        __syncthreads();
        s[threadIdx.x] += t;
        __syncthreads();
    }
    if (threadIdx.x < nb) bsum[threadIdx.x] = s[threadIdx.x] - v;
}
__global__ void k_scanfinal(const int* __restrict__ deg, const int* __restrict__ bsum,
                            int* __restrict__ rowptr, int n, int E) {
    __shared__ int s[256];
    int i = blockIdx.x * 256 + threadIdx.x;
    int v = (i < n) ? deg[i] : 0;
    s[threadIdx.x] = v;
    __syncthreads();
    for (int o = 1; o < 256; o <<= 1) {
        int t = (threadIdx.x >= o) ? s[threadIdx.x - o] : 0;
        __syncthreads();
        s[threadIdx.x] += t;
        __syncthreads();
    }
    if (i < n) rowptr[i] = bsum[blockIdx.x] + s[threadIdx.x] - v;
    if (i == 0 && blockIdx.x == 0) rowptr[n] = E;
}
__global__ void k_fill(const int* __restrict__ row, const int* __restrict__ col,
                       const float* __restrict__ dinv,
                       const int* __restrict__ rowptr, int* __restrict__ counter,
                       int* __restrict__ esrc, float* __restrict__ ew, int E) {
    int e = blockIdx.x * blockDim.x + threadIdx.x;
    if (e >= E) return;
    int r = row[e], t = col[e];
    int p = rowptr[t] + atomicAdd(&counter[t], 1);
    esrc[p] = r;
    ew[p] = dinv[r] * dinv[t];
}

// ---------------- message passing: CSR gather, fp16 source ----------------
// CH chunks of 8 halves per node (across all K planes); F8K chunks per plane.
template<int CH, int F8K>
__global__ void k_prop_h(const __half* __restrict__ src, float* __restrict__ dst,
                         const int* __restrict__ rowptr, const int* __restrict__ esrc,
                         const float* __restrict__ ew, int N, long sKh, long sKf) {
    int idx = blockIdx.x * blockDim.x + threadIdx.x;
    int n = idx / CH;
    if (n >= N) return;
    int c = idx - n * CH;
    int k = c / F8K;
    int cc = c - k * F8K;
    const int F = F8K * 8;
    const __half* sb = src + (long)k * sKh + cc * 8;
    float acc[8];
#pragma unroll
    for (int q = 0; q < 8; q++) acc[q] = 0.f;
    int s0 = rowptr[n], s1 = rowptr[n + 1];
    for (int j = s0; j < s1; j++) {
        int s = esrc[j];
        float wv = ew[j];
        uint4 u = *(const uint4*)(sb + (long)s * F);
        const __half2* hp = (const __half2*)&u;
#pragma unroll
        for (int q = 0; q < 4; q++) {
            float2 f = __half22float2(hp[q]);
            acc[2 * q]     += f.x * wv;
            acc[2 * q + 1] += f.y * wv;
        }
    }
    float* db = dst + (long)k * sKf + ((long)n * F + cc * 8);
    *(float4*)db       = make_float4(acc[0], acc[1], acc[2], acc[3]);
    *(float4*)(db + 4) = make_float4(acc[4], acc[5], acc[6], acc[7]);
}

// ---------------- fused SGEMM: R2-style 4x8 micro-tile, 32*(FO/8) threads ----------------
// C[k] = act( [A1|A2][k] @ [B1;B2][k] + D1[k] + alpha2*D2[k] + bias_scalar )
// meanMode: A-load = 0.5*(A1 + A2) over full Fin (mean over K=2).
template<int FO>
__global__ __launch_bounds__(32 * (FO / 8))
void k_gemm3(const float* __restrict__ A1, long a1K, int fin1, int lda1,
             const float* __restrict__ A2, long a2K, int lda2, int meanMode,
             const float* __restrict__ B1, long b1K,
             const float* __restrict__ B2, long b2K,
             int Fin,
             const float* __restrict__ D1, long dK,
             const float* __restrict__ D2, float alpha2,
             const float* __restrict__ bias,
             float* __restrict__ Cf, __half* __restrict__ Ch, long cK, long chK,
             int nRows, int act) {
    constexpr int TX = FO / 8;
    constexpr int NT = 32 * TX;
    const int k = blockIdx.z;
    A1 += (long)k * a1K;
    const float* a2 = A2 ? (A2 + (long)k * a2K) : nullptr;
    B1 += (long)k * b1K;
    const float* b2p = B2 ? (B2 + (long)k * b2K) : nullptr;
    const float* d1 = D1 ? (D1 + (long)k * dK) : nullptr;
    const float* d2 = D2 ? (D2 + (long)k * dK) : nullptr;
    float* cf = Cf ? (Cf + (long)k * cK) : nullptr;
    __half* ch = Ch ? (Ch + (long)k * chK) : nullptr;

    __shared__ float Bs[128][FO];
    __shared__ float As[128][17];

    const int tid = threadIdx.x;
    const int tx = tid % TX;        // 8 output cols each
    const int ty = tid / TX;        // 0..31, 4 rows each
    const int row0 = blockIdx.x * 128;

    for (int i = tid; i < Fin * FO; i += NT) {
        int r = i / FO;
        ((float*)Bs)[i] = (r < fin1) ? B1[i] : b2p[i - fin1 * FO];
    }

    float acc[4][8];
#pragma unroll
    for (int i = 0; i < 4; i++)
#pragma unroll
        for (int j = 0; j < 8; j++) acc[i][j] = 0.f;

    for (int kk0 = 0; kk0 < Fin; kk0 += 16) {
        __syncthreads();
        for (int i = tid; i < 128 * 16; i += NT) {
            int r = i >> 4, c = i & 15;
            int gr = row0 + r;
            int gc = kk0 + c;
            float v = 0.f;
            if (gr < nRows) {
                if (meanMode)
                    v = 0.5f * (A1[(long)gr * lda1 + gc] + a2[(long)gr * lda2 + gc]);
                else if (gc < fin1)
                    v = A1[(long)gr * lda1 + gc];
                else
                    v = a2[(long)gr * lda2 + gc - fin1];
            }
            As[r][c] = v;
        }
        __syncthreads();
#pragma unroll
        for (int kk = 0; kk < 16; kk++) {
            float4 bA = *(const float4*)&Bs[kk0 + kk][tx * 8];
            float4 bB = *(const float4*)&Bs[kk0 + kk][tx * 8 + 4];
#pragma unroll
            for (int i = 0; i < 4; i++) {
                float a = As[ty * 4 + i][kk];
                acc[i][0] += a * bA.x; acc[i][1] += a * bA.y;
                acc[i][2] += a * bA.z; acc[i][3] += a * bA.w;
                acc[i][4] += a * bB.x; acc[i][5] += a * bB.y;
                acc[i][6] += a * bB.z; acc[i][7] += a * bB.w;
            }
        }
    }

    float bvs = bias ? __ldg(bias) : 0.f;
#pragma unroll
    for (int i = 0; i < 4; i++) {
        int gr = row0 + ty * 4 + i;
        if (gr < nRows) {
            long base = (long)gr * FO + tx * 8;
            float v[8];
#pragma unroll
            for (int j = 0; j < 8; j++) {
                float t = acc[i][j];
                if (d1) t += d1[base + j];
                if (d2) t += alpha2 * d2[base + j];
                t += bvs;
                if (act) t = (t >= 0.f) ? t : 0.2f * t;
                v[j] = t;
            }
            if (cf) {
                *(float4*)(cf + base)     = make_float4(v[0], v[1], v[2], v[3]);
                *(float4*)(cf + base + 4) = make_float4(v[4], v[5], v[6], v[7]);
            }
            if (ch) {
                __half2 h0 = __floats2half2_rn(v[0], v[1]);
                __half2 h1 = __floats2half2_rn(v[2], v[3]);
                __half2 h2 = __floats2half2_rn(v[4], v[5]);
                __half2 h3 = __floats2half2_rn(v[6], v[7]);
                uint4 pk;
                pk.x = *(unsigned*)&h0; pk.y = *(unsigned*)&h1;
                pk.z = *(unsigned*)&h2; pk.w = *(unsigned*)&h3;
                *(uint4*)(ch + base) = pk;
            }
        }
    }
}

// y = relu(a + b) : sum over K=2 stacks + inter-layer ReLU, fp32 + fp16 mirror
__global__ void k_combine(const float4* __restrict__ a, const float4* __restrict__ b,
                          float4* __restrict__ o, __half2* __restrict__ oh, int n4) {
    int i = blockIdx.x * blockDim.x + threadIdx.x;
    if (i < n4) {
        float4 x = a[i], y = b[i];
        float4 r;
        r.x = fmaxf(x.x + y.x, 0.f);
        r.y = fmaxf(x.y + y.y, 0.f);
        r.z = fmaxf(x.z + y.z, 0.f);
        r.w = fmaxf(x.w + y.w, 0.f);
        o[i] = r;
        oh[2 * i]     = __floats2half2_rn(r.x, r.y);
        oh[2 * i + 1] = __floats2half2_rn(r.z, r.w);
    }
}

// warp-per-row log_softmax, C == 32 lanes
__global__ void k_logsoftmax(const float* __restrict__ in, float* __restrict__ out, int n) {
    int warp = (blockIdx.x * blockDim.x + threadIdx.x) >> 5;
    int lane = threadIdx.x & 31;
    if (warp >= n) return;
    float v = in[(long)warp * 32 + lane];
    float m = v;
#pragma unroll
    for (int o = 16; o > 0; o >>= 1) m = fmaxf(m, __shfl_xor_sync(0xffffffffu, m, o));
    float e = expf(v - m);
    float s = e;
#pragma unroll
    for (int o = 16; o > 0; o >>= 1) s += __shfl_xor_sync(0xffffffffu, s, o);
    out[(long)warp * 32 + lane] = v - m - logf(s);
}

// ---------------- host orchestration ----------------
extern "C" void kernel_launch(void* const* d_in, const int* in_sizes, int n_in,
                              void* d_out, int out_size) {
    const float* x = (const float*)d_in[0];
    const int* ei  = (const int*)d_in[1];
    const int E = in_sizes[1] / 2;
    const int N = in_sizes[0] / 128;
    const int* row = ei;
    const int* col = ei + E;

    float *dinv, *h, *b0, *ag, *b2, *b4, *ew;
    __half *hh, *b3h;
    int *deg, *rowptr, *bsum, *esrc;
    cudaGetSymbolAddress((void**)&dinv,   g_dinv);
    cudaGetSymbolAddress((void**)&deg,    g_deg);
    cudaGetSymbolAddress((void**)&rowptr, g_rowptr);
    cudaGetSymbolAddress((void**)&bsum,   g_bsum);
    cudaGetSymbolAddress((void**)&esrc,   g_esrc);
    cudaGetSymbolAddress((void**)&ew,     g_ew);
    cudaGetSymbolAddress((void**)&h,      g_h);
    cudaGetSymbolAddress((void**)&hh,     g_hh);
    cudaGetSymbolAddress((void**)&b3h,    g_b3h);
    cudaGetSymbolAddress((void**)&b0,     g_buf0);
    cudaGetSymbolAddress((void**)&ag,     g_agg);
    cudaGetSymbolAddress((void**)&b2,     g_buf2);
    cudaGetSymbolAddress((void**)&b4,     g_buf4);

    const int nb = (N + 255) / 256;

    // gcn_norm + destination-sorted CSR build
    k_zero_int<<<nb, 256>>>(deg, N);
    k_deg<<<(E + 255) / 256, 256>>>(col, deg, E);
    k_dinv<<<nb, 256>>>(deg, dinv, N);
    k_blocksum<<<nb, 256>>>(deg, bsum, N);
    k_scanb<<<1, 256>>>(bsum, nb);
    k_scanfinal<<<nb, 256>>>(deg, bsum, rowptr, N, E);
    k_zero_int<<<nb, 256>>>(deg, N);
    k_fill<<<(E + 255) / 256, 256>>>(row, col, dinv, rowptr, deg, esrc, ew, E);

    const long sK  = (long)N * 64;     // fp32 plane stride (F=64)
    const int gX   = (N + 127) / 128;

    // -------- Layer 1: Fin=128, FO=64, K=2, T=2 (non-commuted first prop) --------
    {
        const float* w  = (const float*)d_in[2];
        const float* iw = (const float*)d_in[3];
        const float* rw = (const float*)d_in[4];
        const float* dw = (const float*)d_in[5];
        const float* bb = (const float*)d_in[6];
        dim3 gg(gX, 1, 2);
        // out0 = x@iw  (fp32 for dense, fp16 mirror for prop)
        k_gemm3<64><<<gg, 256>>>(x, 0, 128, 128, nullptr, 0, 0, 0,
                                 iw, 128 * 64, nullptr, 0, 128,
                                 nullptr, 0, nullptr, 0.f, nullptr,
                                 b0, b3h, sK, sK, N, 0);
        // agg = prop(out0)
        k_prop_h<16, 8><<<(int)((((long)N * 16) + 255) / 256), 256>>>(b3h, ag, rowptr, esrc, ew, N, sK, sK);
        // out_t0 = leaky(agg + x@rw0 + b0)
        k_gemm3<64><<<gg, 256>>>(x, 0, 128, 128, nullptr, 0, 0, 0,
                                 rw, 128 * 64, nullptr, 0, 128,
                                 ag, sK, nullptr, 0.f, bb + 0,
                                 b2, nullptr, sK, 0, N, 1);
        // t1 = out_t0@W[0]  (fp16 only)
        k_gemm3<64><<<gg, 256>>>(b2, sK, 64, 64, nullptr, 0, 0, 0,
                                 w, 64 * 64, nullptr, 0, 64,
                                 nullptr, 0, nullptr, 0.f, nullptr,
                                 nullptr, b3h, 0, sK, N, 0);
        // agg2 = prop(t1)
        k_prop_h<16, 8><<<(int)((((long)N * 16) + 255) / 256), 256>>>(b3h, ag, rowptr, esrc, ew, N, sK, sK);
        // dense1 = mean_k(out0)@dw[1]
        k_gemm3<64><<<gg, 256>>>(b0, 0, 64, 64, b0 + sK, 0, 64, 1,
                                 dw + 2 * 64 * 64, 64 * 64, nullptr, 0, 64,
                                 nullptr, 0, nullptr, 0.f, nullptr,
                                 b4, nullptr, sK, 0, N, 0);
        // final = leaky(agg2 + x@rw1 + 0.6*dense1 + b1)
        k_gemm3<64><<<gg, 256>>>(x, 0, 128, 128, nullptr, 0, 0, 0,
                                 rw + 2 * 128 * 64, 128 * 64, nullptr, 0, 128,
                                 ag, sK, b4, 0.6f, bb + 1,
                                 b2, nullptr, sK, 0, N, 1);
        int n4 = (int)(sK / 4);
        k_combine<<<(n4 + 255) / 256, 256>>>((const float4*)b2, (const float4*)(b2 + sK),
                                             (float4*)h, (__half2*)hh, n4);
    }

    // -------- Layers 2-5: Fin=64, FO=64, K=2, T=2 (commuted first prop) --------
    for (int L = 1; L < 5; L++) {
        const float* w  = (const float*)d_in[2 + L * 5 + 0];
        const float* iw = (const float*)d_in[2 + L * 5 + 1];
        const float* rw = (const float*)d_in[2 + L * 5 + 2];
        const float* dw = (const float*)d_in[2 + L * 5 + 3];
        const float* bb = (const float*)d_in[2 + L * 5 + 4];
        dim3 gg(gX, 1, 2);
        // pc = prop(h)  (single shared plane)
        k_prop_h<8, 8><<<(int)((((long)N * 8) + 255) / 256), 256>>>(hh, ag, rowptr, esrc, ew, N, 0, 0);
        // out0 = h@iw (fp32, dense path only)
        k_gemm3<64><<<gg, 256>>>(h, 0, 64, 64, nullptr, 0, 0, 0,
                                 iw, 64 * 64, nullptr, 0, 64,
                                 nullptr, 0, nullptr, 0.f, nullptr,
                                 b0, nullptr, sK, 0, N, 0);
        // out_t0 = leaky([pc|h] @ [iw;rw0] + b0)
        k_gemm3<64><<<gg, 256>>>(ag, 0, 64, 64, h, 0, 64, 0,
                                 iw, 64 * 64, rw, 64 * 64, 128,
                                 nullptr, 0, nullptr, 0.f, bb + 0,
                                 b2, nullptr, sK, 0, N, 1);
        // t1 = out_t0@W[0]  (fp16 only)
        k_gemm3<64><<<gg, 256>>>(b2, sK, 64, 64, nullptr, 0, 0, 0,
                                 w, 64 * 64, nullptr, 0, 64,
                                 nullptr, 0, nullptr, 0.f, nullptr,
                                 nullptr, b3h, 0, sK, N, 0);
        // agg2 = prop(t1)
        k_prop_h<16, 8><<<(int)((((long)N * 16) + 255) / 256), 256>>>(b3h, ag, rowptr, esrc, ew, N, sK, sK);
        // dense1 = mean_k(out0)@dw[1]
        k_gemm3<64><<<gg, 256>>>(b0, 0, 64, 64, b0 + sK, 0, 64, 1,
                                 dw + 2 * 64 * 64, 64 * 64, nullptr, 0, 64,
                                 nullptr, 0, nullptr, 0.f, nullptr,
                                 b4, nullptr, sK, 0, N, 0);
        // final = leaky(agg2 + h@rw1 + 0.6*dense1 + b1)
        k_gemm3<64><<<gg, 256>>>(h, 0, 64, 64, nullptr, 0, 0, 0,
                                 rw + 2 * 64 * 64, 64 * 64, nullptr, 0, 64,
                                 ag, sK, b4, 0.6f, bb + 1,
                                 b2, nullptr, sK, 0, N, 1);
        int n4 = (int)(sK / 4);
        k_combine<<<(n4 + 255) / 256, 256>>>((const float4*)b2, (const float4*)(b2 + sK),
                                             (float4*)h, (__half2*)hh, n4);
    }

    // -------- Layer 6: Fin=64, FO=32, K=1, T=1 (commuted) --------
    {
        const float* iw = (const float*)d_in[2 + 5 * 5 + 1];
        const float* rw = (const float*)d_in[2 + 5 * 5 + 2];
        const float* bb = (const float*)d_in[2 + 5 * 5 + 4];
        // pc = prop(h)
        k_prop_h<8, 8><<<(int)((((long)N * 8) + 255) / 256), 256>>>(hh, ag, rowptr, esrc, ew, N, 0, 0);
        // out = leaky([pc|h] @ [iw;rw] + b0)
        dim3 gg(gX, 1, 1);
        k_gemm3<32><<<gg, 128>>>(ag, 0, 64, 64, h, 0, 64, 0,
                                 iw, 64 * 32, rw, 64 * 32, 128,
                                 nullptr, 0, nullptr, 0.f, bb + 0,
                                 b2, nullptr, (long)N * 32, 0, N, 1);
        k_logsoftmax<<<(N + 7) / 8, 256>>>(b2, (float*)d_out, N);
    }
    (void)n_in; (void)out_size;
}

// round 7
// speedup vs baseline: 2.3548x; 2.0041x over previous
#include <cuda_runtime.h>
#include <cuda_fp16.h>
#include <math.h>

#define NN 50000
#define EE 800000

// ---------------- scratch (static device globals; no allocations) ----------------
__device__ float  g_dinv[NN];
__device__ int    g_deg[NN];
__device__ int    g_rowptr[NN + 1];
__device__ int    g_bsum[256];
__device__ int    g_esrc[EE];
__device__ float  g_ew[EE];
__device__ float  g_h   [(size_t)NN * 64];       // inter-layer activations (fp32)
__device__ __half g_hh  [(size_t)NN * 64];       // fp16 mirror of h
__device__ __half g_b3h [(size_t)2 * NN * 64];   // fp16: out0 mirror (L1) / t1 output
__device__ float  g_buf0[(size_t)2 * NN * 64];   // out0 (for dense path)
__device__ float  g_agg [(size_t)2 * NN * 64];   // prop destination (pc / agg2)
__device__ float  g_buf2[(size_t)2 * NN * 64];   // t0 output / final per-k
__device__ float  g_buf4[(size_t)2 * NN * 64];   // dense1

// ---------------- setup kernels ----------------
__global__ void k_zero_int(int* p, int n) {
    int i = blockIdx.x * blockDim.x + threadIdx.x;
    if (i < n) p[i] = 0;
}
__global__ void k_deg(const int* __restrict__ col, int* __restrict__ deg, int E) {
    int e = blockIdx.x * blockDim.x + threadIdx.x;
    if (e < E) atomicAdd(&deg[col[e]], 1);
}
__global__ void k_dinv(const int* __restrict__ deg, float* __restrict__ dinv, int n) {
    int i = blockIdx.x * blockDim.x + threadIdx.x;
    if (i < n) {
        int d = deg[i];
        dinv[i] = (d > 0) ? rsqrtf((float)d) : 0.f;
    }
}
__global__ void k_blocksum(const int* __restrict__ deg, int* __restrict__ bsum, int n) {
    __shared__ int s[256];
    int i = blockIdx.x * 256 + threadIdx.x;
    s[threadIdx.x] = (i < n) ? deg[i] : 0;
    __syncthreads();
    for (int o = 128; o > 0; o >>= 1) {
        if (threadIdx.x < o) s[threadIdx.x] += s[threadIdx.x + o];
        __syncthreads();
    }
    if (threadIdx.x == 0) bsum[blockIdx.x] = s[0];
}
__global__ void k_scanb(int* bsum, int nb) {
    __shared__ int s[256];
    int v = (threadIdx.x < nb) ? bsum[threadIdx.x] : 0;
    s[threadIdx.x] = v;
    __syncthreads();
    for (int o = 1; o < 256; o <<= 1) {
        int t = (threadIdx.x >= o) ? s[threadIdx.x - o] : 0;
        __syncthreads();
        s[threadIdx.x] += t;
        __syncthreads();
    }
    if (threadIdx.x < nb) bsum[threadIdx.x] = s[threadIdx.x] - v;
}
__global__ void k_scanfinal(const int* __restrict__ deg, const int* __restrict__ bsum,
                            int* __restrict__ rowptr, int n, int E) {
    __shared__ int s[256];
    int i = blockIdx.x * 256 + threadIdx.x;
    int v = (i < n) ? deg[i] : 0;
    s[threadIdx.x] = v;
    __syncthreads();
    for (int o = 1; o < 256; o <<= 1) {
        int t = (threadIdx.x >= o) ? s[threadIdx.x - o] : 0;
        __syncthreads();
        s[threadIdx.x] += t;
        __syncthreads();
    }
    if (i < n) rowptr[i] = bsum[blockIdx.x] + s[threadIdx.x] - v;
    if (i == 0 && blockIdx.x == 0) rowptr[n] = E;
}
__global__ void k_fill(const int* __restrict__ row, const int* __restrict__ col,
                       const float* __restrict__ dinv,
                       const int* __restrict__ rowptr, int* __restrict__ counter,
                       int* __restrict__ esrc, float* __restrict__ ew, int E) {
    int e = blockIdx.x * blockDim.x + threadIdx.x;
    if (e >= E) return;
    int r = row[e], t = col[e];
    int p = rowptr[t] + atomicAdd(&counter[t], 1);
    esrc[p] = r;
    ew[p] = dinv[r] * dinv[t];
}

// ---------------- message passing: CSR gather, fp16 source ----------------
template<int CH, int F8K>
__global__ void k_prop_h(const __half* __restrict__ src, float* __restrict__ dst,
                         const int* __restrict__ rowptr, const int* __restrict__ esrc,
                         const float* __restrict__ ew, int N, long sKh, long sKf) {
    int idx = blockIdx.x * blockDim.x + threadIdx.x;
    int n = idx / CH;
    if (n >= N) return;
    int c = idx - n * CH;
    int k = c / F8K;
    int cc = c - k * F8K;
    const int F = F8K * 8;
    const __half* sb = src + (long)k * sKh + cc * 8;
    float acc[8];
#pragma unroll
    for (int q = 0; q < 8; q++) acc[q] = 0.f;
    int s0 = rowptr[n], s1 = rowptr[n + 1];
    for (int j = s0; j < s1; j++) {
        int s = esrc[j];
        float wv = ew[j];
        uint4 u = *(const uint4*)(sb + (long)s * F);
        const __half2* hp = (const __half2*)&u;
#pragma unroll
        for (int q = 0; q < 4; q++) {
            float2 f = __half22float2(hp[q]);
            acc[2 * q]     += f.x * wv;
            acc[2 * q + 1] += f.y * wv;
        }
    }
    float* db = dst + (long)k * sKf + ((long)n * F + cc * 8);
    *(float4*)db       = make_float4(acc[0], acc[1], acc[2], acc[3]);
    *(float4*)(db + 4) = make_float4(acc[4], acc[5], acc[6], acc[7]);
}

// ---------------- tf32 tensor-core helpers ----------------
__device__ __forceinline__ float to_tf32(float x) {
    unsigned u;
    asm("cvt.rna.tf32.f32 %0, %1;" : "=r"(u) : "f"(x));
    return __uint_as_float(u);
}
__device__ __forceinline__ void mma_tf32(float* c, float a0, float a1, float a2, float a3,
                                         float b0, float b1) {
    asm volatile(
        "mma.sync.aligned.m16n8k8.row.col.f32.tf32.tf32.f32 "
        "{%0,%1,%2,%3}, {%4,%5,%6,%7}, {%8,%9}, {%0,%1,%2,%3};\n"
        : "+f"(c[0]), "+f"(c[1]), "+f"(c[2]), "+f"(c[3])
        : "r"(__float_as_uint(a0)), "r"(__float_as_uint(a1)),
          "r"(__float_as_uint(a2)), "r"(__float_as_uint(a3)),
          "r"(__float_as_uint(b0)), "r"(__float_as_uint(b1)));
}

// ---------------- fused GEMM via tf32 mma.sync ----------------
// C[k] = act( [A1|A2][k] @ [B1;B2][k] + D1[k] + alpha2*D2[k] + bias_scalar )
// meanMode: A-load = 0.5*(A1 + A2) over full Fin (fin1 == Fin).
// Block: 128 rows x FO cols, 256 threads (8 warps x 16 rows). K chunks of 32.
template<int FO>
__global__ __launch_bounds__(256)
void k_gemm_tc(const float* __restrict__ A1, long a1K, int fin1, int lda1,
               const float* __restrict__ A2, long a2K, int lda2, int meanMode,
               const float* __restrict__ B1, long b1K,
               const float* __restrict__ B2, long b2K,
               int Fin,
               const float* __restrict__ D1, long dK,
               const float* __restrict__ D2, float alpha2,
               const float* __restrict__ bias,
               float* __restrict__ Cf, __half* __restrict__ Ch, long cK, long chK,
               int nRows, int act) {
    constexpr int NT = FO / 8;                 // n-tiles per warp row-band
    __shared__ float As[128][36];              // 32-K chunk, pad 36: banks=4g+tg (bijective)
    __shared__ float Bf[4 * NT * 32 * 2];      // B fragments for current chunk

    const int k = blockIdx.z;
    const float* a1p = A1 + (long)k * a1K;
    const float* a2p = A2 ? (A2 + (long)k * a2K) : nullptr;
    const float* b1p = B1 + (long)k * b1K;
    const float* b2p = B2 ? (B2 + (long)k * b2K) : nullptr;
    const float* d1 = D1 ? (D1 + (long)k * dK) : nullptr;
    const float* d2 = D2 ? (D2 + (long)k * dK) : nullptr;
    float* cf = Cf ? (Cf + (long)k * cK) : nullptr;
    __half* ch = Ch ? (Ch + (long)k * chK) : nullptr;

    const int tid = threadIdx.x;
    const int lane = tid & 31;
    const int warp = tid >> 5;
    const int g  = lane >> 2;   // 0..7
    const int tg = lane & 3;    // 0..3
    const int row0 = blockIdx.x * 128;
    const int wr = warp * 16;

    float acc[NT][4];
#pragma unroll
    for (int nt = 0; nt < NT; nt++)
#pragma unroll
        for (int q = 0; q < 4; q++) acc[nt][q] = 0.f;

    for (int kc = 0; kc < Fin; kc += 32) {
        __syncthreads();   // protect previous chunk's smem from overwrite
        // ---- load A chunk 128x32 -> As (tf32), float4 vectorized ----
        const float* Asrc; int lda, coff;
        if (meanMode || kc < fin1) { Asrc = a1p; lda = lda1; coff = kc; }
        else                        { Asrc = a2p; lda = lda2; coff = kc - fin1; }
        for (int i = tid; i < 128 * 8; i += 256) {
            int r = i >> 3, c4 = (i & 7) * 4;
            int gr = row0 + r;
            float4 v = make_float4(0.f, 0.f, 0.f, 0.f);
            if (gr < nRows) {
                v = *(const float4*)(Asrc + (long)gr * lda + coff + c4);
                if (meanMode) {
                    float4 u = *(const float4*)(a2p + (long)gr * lda2 + coff + c4);
                    v.x = 0.5f * (v.x + u.x); v.y = 0.5f * (v.y + u.y);
                    v.z = 0.5f * (v.z + u.z); v.w = 0.5f * (v.w + u.w);
                }
            }
            v.x = to_tf32(v.x); v.y = to_tf32(v.y); v.z = to_tf32(v.z); v.w = to_tf32(v.w);
            *(float4*)&As[r][c4] = v;
        }
        // ---- pack B chunk (32 x FO) into mma fragment order ----
        for (int i = tid; i < 4 * NT * 64; i += 256) {
            int r2 = i & 1;
            int lane2 = (i >> 1) & 31;
            int nt = (i >> 6) % NT;
            int ks = i / (64 * NT);
            int tg2 = lane2 & 3, g2 = lane2 >> 2;
            int kl = ks * 8 + tg2 + r2 * 4;
            int n  = nt * 8 + g2;
            int kg = kc + kl;
            float bv = (kg < fin1) ? b1p[kg * FO + n] : b2p[(kg - fin1) * FO + n];
            Bf[i] = to_tf32(bv);
        }
        __syncthreads();
        // ---- compute: 4 k-steps of 8 ----
#pragma unroll
        for (int ks = 0; ks < 4; ks++) {
            float a0 = As[wr + g][ks * 8 + tg];
            float a1 = As[wr + g + 8][ks * 8 + tg];
            float a2 = As[wr + g][ks * 8 + tg + 4];
            float a3 = As[wr + g + 8][ks * 8 + tg + 4];
#pragma unroll
            for (int nt = 0; nt < NT; nt++) {
                float2 b = *(const float2*)&Bf[((ks * NT + nt) * 32 + lane) * 2];
                mma_tf32(acc[nt], a0, a1, a2, a3, b.x, b.y);
            }
        }
    }

    // ---- epilogue: fragment c0..c3 -> (r0,cb),(r0,cb+1),(r1,cb),(r1,cb+1) ----
    float bvs = bias ? __ldg(bias) : 0.f;
    int r0 = row0 + wr + g;
    int r1 = r0 + 8;
#pragma unroll
    for (int nt = 0; nt < NT; nt++) {
        int cb = nt * 8 + tg * 2;
#pragma unroll
        for (int half = 0; half < 2; half++) {
            int gr = half ? r1 : r0;
            if (gr < nRows) {
                long base = (long)gr * FO + cb;
                float v0 = acc[nt][half * 2 + 0];
                float v1 = acc[nt][half * 2 + 1];
                if (d1) { float2 dd = *(const float2*)(d1 + base); v0 += dd.x; v1 += dd.y; }
                if (d2) { float2 dd = *(const float2*)(d2 + base); v0 += alpha2 * dd.x; v1 += alpha2 * dd.y; }
                v0 += bvs; v1 += bvs;
                if (act) {
                    v0 = (v0 >= 0.f) ? v0 : 0.2f * v0;
                    v1 = (v1 >= 0.f) ? v1 : 0.2f * v1;
                }
                if (cf) *(float2*)(cf + base) = make_float2(v0, v1);
                if (ch) *(__half2*)(ch + base) = __floats2half2_rn(v0, v1);
            }
        }
    }
}

// y = relu(a + b) : sum over K=2 stacks + inter-layer ReLU, fp32 + fp16 mirror
__global__ void k_combine(const float4* __restrict__ a, const float4* __restrict__ b,
                          float4* __restrict__ o, __half2* __restrict__ oh, int n4) {
    int i = blockIdx.x * blockDim.x + threadIdx.x;
    if (i < n4) {
        float4 x = a[i], y = b[i];
        float4 r;
        r.x = fmaxf(x.x + y.x, 0.f);
        r.y = fmaxf(x.y + y.y, 0.f);
        r.z = fmaxf(x.z + y.z, 0.f);
        r.w = fmaxf(x.w + y.w, 0.f);
        o[i] = r;
        oh[2 * i]     = __floats2half2_rn(r.x, r.y);
        oh[2 * i + 1] = __floats2half2_rn(r.z, r.w);
    }
}

// warp-per-row log_softmax, C == 32 lanes
__global__ void k_logsoftmax(const float* __restrict__ in, float* __restrict__ out, int n) {
    int warp = (blockIdx.x * blockDim.x + threadIdx.x) >> 5;
    int lane = threadIdx.x & 31;
    if (warp >= n) return;
    float v = in[(long)warp * 32 + lane];
    float m = v;
#pragma unroll
    for (int o = 16; o > 0; o >>= 1) m = fmaxf(m, __shfl_xor_sync(0xffffffffu, m, o));
    float e = expf(v - m);
    float s = e;
#pragma unroll
    for (int o = 16; o > 0; o >>= 1) s += __shfl_xor_sync(0xffffffffu, s, o);
    out[(long)warp * 32 + lane] = v - m - logf(s);
}

// ---------------- host orchestration ----------------
extern "C" void kernel_launch(void* const* d_in, const int* in_sizes, int n_in,
                              void* d_out, int out_size) {
    const float* x = (const float*)d_in[0];
    const int* ei  = (const int*)d_in[1];
    const int E = in_sizes[1] / 2;
    const int N = in_sizes[0] / 128;
    const int* row = ei;
    const int* col = ei + E;

    float *dinv, *h, *b0, *ag, *b2, *b4, *ew;
    __half *hh, *b3h;
    int *deg, *rowptr, *bsum, *esrc;
    cudaGetSymbolAddress((void**)&dinv,   g_dinv);
    cudaGetSymbolAddress((void**)&deg,    g_deg);
    cudaGetSymbolAddress((void**)&rowptr, g_rowptr);
    cudaGetSymbolAddress((void**)&bsum,   g_bsum);
    cudaGetSymbolAddress((void**)&esrc,   g_esrc);
    cudaGetSymbolAddress((void**)&ew,     g_ew);
    cudaGetSymbolAddress((void**)&h,      g_h);
    cudaGetSymbolAddress((void**)&hh,     g_hh);
    cudaGetSymbolAddress((void**)&b3h,    g_b3h);
    cudaGetSymbolAddress((void**)&b0,     g_buf0);
    cudaGetSymbolAddress((void**)&ag,     g_agg);
    cudaGetSymbolAddress((void**)&b2,     g_buf2);
    cudaGetSymbolAddress((void**)&b4,     g_buf4);

    const int nb = (N + 255) / 256;

    // gcn_norm + destination-sorted CSR build
    k_zero_int<<<nb, 256>>>(deg, N);
    k_deg<<<(E + 255) / 256, 256>>>(col, deg, E);
    k_dinv<<<nb, 256>>>(deg, dinv, N);
    k_blocksum<<<nb, 256>>>(deg, bsum, N);
    k_scanb<<<1, 256>>>(bsum, nb);
    k_scanfinal<<<nb, 256>>>(deg, bsum, rowptr, N, E);
    k_zero_int<<<nb, 256>>>(deg, N);
    k_fill<<<(E + 255) / 256, 256>>>(row, col, dinv, rowptr, deg, esrc, ew, E);

    const long sK  = (long)N * 64;     // fp32 plane stride (F=64)
    const int gX   = (N + 127) / 128;

    // -------- Layer 1: Fin=128, FO=64, K=2, T=2 (non-commuted first prop) --------
    {
        const float* w  = (const float*)d_in[2];
        const float* iw = (const float*)d_in[3];
        const float* rw = (const float*)d_in[4];
        const float* dw = (const float*)d_in[5];
        const float* bb = (const float*)d_in[6];
        dim3 gg(gX, 1, 2);
        // out0 = x@iw  (fp32 for dense, fp16 mirror for prop)
        k_gemm_tc<64><<<gg, 256>>>(x, 0, 128, 128, nullptr, 0, 0, 0,
                                   iw, 128 * 64, nullptr, 0, 128,
                                   nullptr, 0, nullptr, 0.f, nullptr,
                                   b0, b3h, sK, sK, N, 0);
        // agg = prop(out0)
        k_prop_h<16, 8><<<(int)((((long)N * 16) + 255) / 256), 256>>>(b3h, ag, rowptr, esrc, ew, N, sK, sK);
        // out_t0 = leaky(agg + x@rw0 + b0)
        k_gemm_tc<64><<<gg, 256>>>(x, 0, 128, 128, nullptr, 0, 0, 0,
                                   rw, 128 * 64, nullptr, 0, 128,
                                   ag, sK, nullptr, 0.f, bb + 0,
                                   b2, nullptr, sK, 0, N, 1);
        // t1 = out_t0@W[0]  (fp16 only)
        k_gemm_tc<64><<<gg, 256>>>(b2, sK, 64, 64, nullptr, 0, 0, 0,
                                   w, 64 * 64, nullptr, 0, 64,
                                   nullptr, 0, nullptr, 0.f, nullptr,
                                   nullptr, b3h, 0, sK, N, 0);
        // agg2 = prop(t1)
        k_prop_h<16, 8><<<(int)((((long)N * 16) + 255) / 256), 256>>>(b3h, ag, rowptr, esrc, ew, N, sK, sK);
        // dense1 = mean_k(out0)@dw[1]
        k_gemm_tc<64><<<gg, 256>>>(b0, 0, 64, 64, b0 + sK, 0, 64, 1,
                                   dw + 2 * 64 * 64, 64 * 64, nullptr, 0, 64,
                                   nullptr, 0, nullptr, 0.f, nullptr,
                                   b4, nullptr, sK, 0, N, 0);
        // final = leaky(agg2 + x@rw1 + 0.6*dense1 + b1)
        k_gemm_tc<64><<<gg, 256>>>(x, 0, 128, 128, nullptr, 0, 0, 0,
                                   rw + 2 * 128 * 64, 128 * 64, nullptr, 0, 128,
                                   ag, sK, b4, 0.6f, bb + 1,
                                   b2, nullptr, sK, 0, N, 1);
        int n4 = (int)(sK / 4);
        k_combine<<<(n4 + 255) / 256, 256>>>((const float4*)b2, (const float4*)(b2 + sK),
                                             (float4*)h, (__half2*)hh, n4);
    }

    // -------- Layers 2-5: Fin=64, FO=64, K=2, T=2 (commuted first prop) --------
    for (int L = 1; L < 5; L++) {
        const float* w  = (const float*)d_in[2 + L * 5 + 0];
        const float* iw = (const float*)d_in[2 + L * 5 + 1];
        const float* rw = (const float*)d_in[2 + L * 5 + 2];
        const float* dw = (const float*)d_in[2 + L * 5 + 3];
        const float* bb = (const float*)d_in[2 + L * 5 + 4];
        dim3 gg(gX, 1, 2);
        // pc = prop(h)  (single shared plane)
        k_prop_h<8, 8><<<(int)((((long)N * 8) + 255) / 256), 256>>>(hh, ag, rowptr, esrc, ew, N, 0, 0);
        // out0 = h@iw (fp32, dense path only)
        k_gemm_tc<64><<<gg, 256>>>(h, 0, 64, 64, nullptr, 0, 0, 0,
                                   iw, 64 * 64, nullptr, 0, 64,
                                   nullptr, 0, nullptr, 0.f, nullptr,
                                   b0, nullptr, sK, 0, N, 0);
        // out_t0 = leaky([pc|h] @ [iw;rw0] + b0)
        k_gemm_tc<64><<<gg, 256>>>(ag, 0, 64, 64, h, 0, 64, 0,
                                   iw, 64 * 64, rw, 64 * 64, 128,
                                   nullptr, 0, nullptr, 0.f, bb + 0,
                                   b2, nullptr, sK, 0, N, 1);
        // t1 = out_t0@W[0]  (fp16 only)
        k_gemm_tc<64><<<gg, 256>>>(b2, sK, 64, 64, nullptr, 0, 0, 0,
                                   w, 64 * 64, nullptr, 0, 64,
                                   nullptr, 0, nullptr, 0.f, nullptr,
                                   nullptr, b3h, 0, sK, N, 0);
        // agg2 = prop(t1)
        k_prop_h<16, 8><<<(int)((((long)N * 16) + 255) / 256), 256>>>(b3h, ag, rowptr, esrc, ew, N, sK, sK);
        // dense1 = mean_k(out0)@dw[1]
        k_gemm_tc<64><<<gg, 256>>>(b0, 0, 64, 64, b0 + sK, 0, 64, 1,
                                   dw + 2 * 64 * 64, 64 * 64, nullptr, 0, 64,
                                   nullptr, 0, nullptr, 0.f, nullptr,
                                   b4, nullptr, sK, 0, N, 0);
        // final = leaky(agg2 + h@rw1 + 0.6*dense1 + b1)
        k_gemm_tc<64><<<gg, 256>>>(h, 0, 64, 64, nullptr, 0, 0, 0,
                                   rw + 2 * 64 * 64, 64 * 64, nullptr, 0, 64,
                                   ag, sK, b4, 0.6f, bb + 1,
                                   b2, nullptr, sK, 0, N, 1);
        int n4 = (int)(sK / 4);
        k_combine<<<(n4 + 255) / 256, 256>>>((const float4*)b2, (const float4*)(b2 + sK),
                                             (float4*)h, (__half2*)hh, n4);
    }

    // -------- Layer 6: Fin=64, FO=32, K=1, T=1 (commuted) --------
    {
        const float* iw = (const float*)d_in[2 + 5 * 5 + 1];
        const float* rw = (const float*)d_in[2 + 5 * 5 + 2];
        const float* bb = (const float*)d_in[2 + 5 * 5 + 4];
        // pc = prop(h)
        k_prop_h<8, 8><<<(int)((((long)N * 8) + 255) / 256), 256>>>(hh, ag, rowptr, esrc, ew, N, 0, 0);
        // out = leaky([pc|h] @ [iw;rw] + b0)
        dim3 gg(gX, 1, 1);
        k_gemm_tc<32><<<gg, 256>>>(ag, 0, 64, 64, h, 0, 64, 0,
                                   iw, 64 * 32, rw, 64 * 32, 128,
                                   nullptr, 0, nullptr, 0.f, bb + 0,
                                   b2, nullptr, (long)N * 32, 0, N, 1);
        k_logsoftmax<<<(N + 7) / 8, 256>>>(b2, (float*)d_out, N);
    }
    (void)n_in; (void)out_size;
}